// round 11
// baseline (speedup 1.0000x reference)
#include <cuda_runtime.h>
#include <math.h>

#define NB 16
#define NN 2048
#define NK 20
#define NC 64
#define RS 132    // padded row stride for smem tiles (breaks multi-row bank overlap)

typedef unsigned long long u64;

// ---- scratch (static __device__, allocation-free) ----
__device__ int   g_idxT[NB*NK*NN];          // knn indices, [b][k][n]
__device__ float g_bxT [NB*NN*NC];          // act_g * (basis_W @ x), point-major [p][c]
__device__ float g_cst [NB*NN*NC];          // edge_g*((We2-We1)@x) + edge_be, [p][o]
__device__ float g_glT [NB*NK*32*NN];       // glf transposed to [b][k][c][n]

// ---- packed f32x2 helpers (Blackwell FFMA2) ----
__device__ __forceinline__ u64 f2pack(float lo, float hi) {
    u64 r; asm("mov.b64 %0, {%1, %2};" : "=l"(r) : "f"(lo), "f"(hi)); return r;
}
__device__ __forceinline__ void f2unpack(u64 v, float& lo, float& hi) {
    asm("mov.b64 {%0, %1}, %2;" : "=f"(lo), "=f"(hi) : "l"(v));
}
__device__ __forceinline__ void ffma2(u64& d, u64 a, u64 b) {
    asm("fma.rn.f32x2 %0, %1, %2, %3;" : "=l"(d) : "l"(a), "l"(b), "l"(d));
}

#define LEAKY(v) ((v) > 0.f ? (v) : 0.2f*(v))

// =====================================================================
// KNN, warp-cooperative (round-9 version; ~195us)
// =====================================================================
__global__ void __launch_bounds__(256)
knn_kernel(const float* __restrict__ pos)
{
    __shared__ float4 sp[NN];
    const int b    = blockIdx.y;
    const int tid  = threadIdx.x;
    const int w    = tid >> 5;
    const int lane = tid & 31;
    const float* pb = pos + (size_t)b*3*NN;
    for (int m = tid; m < NN; m += 256) {
        float xx = pb[m], yy = pb[NN + m], zz = pb[2*NN + m];
        sp[m] = make_float4(xx, yy, zz, xx*xx + yy*yy + zz*zz);
    }
    __syncthreads();

    const int qbase = blockIdx.x*32 + w*4;
    #pragma unroll 1
    for (int qi = 0; qi < 4; qi++) {
        const int q = qbase + qi;
        const float4 pq = sp[q];
        float v = -1e30f;
        int   idx = 0;

        #pragma unroll 1
        for (int blk = 0; blk < NN; blk += 32) {
            const int m = blk + lane;
            float4 pm = sp[m];
            float pd = 2.0f*(pq.x*pm.x + pq.y*pm.y + pq.z*pm.z) - pq.w - pm.w;
            pd = (m == q) ? -1e30f : pd;
            float t20 = __shfl_sync(0xFFFFFFFFu, v, 19);
            unsigned mask = __ballot_sync(0xFFFFFFFFu, pd > t20);
            while (mask) {
                int src = __ffs((int)mask) - 1;
                float pdv = __shfl_sync(0xFFFFFFFFu, pd, src);
                mask &= mask - 1;
                unsigned cmp = __ballot_sync(0xFFFFFFFFu, pdv > v) & 0xFFFFFu;
                if (cmp) {
                    int pos = __ffs((int)cmp) - 1;
                    float nv = __shfl_up_sync(0xFFFFFFFFu, v, 1);
                    int  nid = __shfl_up_sync(0xFFFFFFFFu, idx, 1);
                    if (lane > pos)  { v = nv;  idx = nid; }
                    if (lane == pos) { v = pdv; idx = blk + src; }
                }
            }
        }
        if (lane < NK)
            g_idxT[((size_t)b*NK + lane)*NN + q] = idx;
    }
}

// =====================================================================
// prep (unchanged)
// =====================================================================
__global__ void prep_kernel(const float* __restrict__ x,
                            const float* __restrict__ basis_W,
                            const float* __restrict__ edge_W,
                            const float* __restrict__ act_g,
                            const float* __restrict__ edge_g,
                            const float* __restrict__ edge_be)
{
    __shared__ float sB[64*64];
    __shared__ float sD[64*64];
    __shared__ float sag[64], seg[64], seb[64];
    const int tid = threadIdx.x;
    for (int i = tid; i < 4096; i += blockDim.x) {
        sB[i] = basis_W[i];
        int o = i >> 6, c = i & 63;
        sD[i] = edge_W[o*128 + 64 + c] - edge_W[o*128 + c];
    }
    for (int i = tid; i < 64; i += blockDim.x) {
        sag[i] = act_g[i]; seg[i] = edge_g[i]; seb[i] = edge_be[i];
    }
    __syncthreads();

    const int p = blockIdx.x * blockDim.x + tid;
    const int b = p / NN, n = p % NN;
    const float* xp = x + (size_t)b*64*NN + n;
    float xv[64];
    #pragma unroll
    for (int c = 0; c < 64; c++) xv[c] = xp[(size_t)c*NN];

    float* bo = g_bxT + (size_t)p*64;
    #pragma unroll 4
    for (int o = 0; o < 64; o++) {
        float acc = 0.f;
        #pragma unroll
        for (int c = 0; c < 64; c++) acc += sB[o*64+c]*xv[c];
        bo[o] = acc * sag[o];
    }
    float* co = g_cst + (size_t)p*64;
    #pragma unroll 4
    for (int o = 0; o < 64; o++) {
        float acc = 0.f;
        #pragma unroll
        for (int c = 0; c < 64; c++) acc += sD[o*64+c]*xv[c];
        co[o] = acc*seg[o] + seb[o];
    }
}

// =====================================================================
// glf transpose (unchanged)
// =====================================================================
__global__ void tr_kernel(const float* __restrict__ glf)
{
    __shared__ float s[64*21];
    const int n0 = blockIdx.x * 64;
    const int c  = blockIdx.y;
    const int b  = blockIdx.z;
    const int tid = threadIdx.x;
    const float* in = glf + (((size_t)b*32 + c)*NN + n0) * NK;
    #pragma unroll
    for (int u = 0; u < 5; u++) {
        int f = tid + u*256;
        int n = f / 20, k = f % 20;
        s[n*21 + k] = in[f];
    }
    __syncthreads();
    #pragma unroll
    for (int u = 0; u < 5; u++) {
        int f = tid + u*256;
        int k = f >> 6, n = f & 63;
        g_glT[(((size_t)b*NK + k)*32 + c)*NN + n0 + n] = s[n*21 + k];
    }
}

// =====================================================================
// main fused kernel: 256 thr, 128-pt tile.
// GEMM2..5 retiled: warp tile 32o(16o)x32p, lane tile 4o(2o)x8p.
// Accumulators packed over POINT pairs -> B operands load as u64
// directly from smem (no packs); weights packed (few packs).
// =====================================================================
__global__ void __launch_bounds__(256, 2)
main_kernel(const float* __restrict__ appf,
            const float* __restrict__ dk_W1, const float* __restrict__ dk_b1,
            const float* __restrict__ dk_g1, const float* __restrict__ dk_be1,
            const float* __restrict__ dk_W2, const float* __restrict__ dk_b2,
            const float* __restrict__ act_b,
            const float* __restrict__ ff_W1, const float* __restrict__ ff_g1,
            const float* __restrict__ ff_be1, const float* __restrict__ ff_W2,
            const float* __restrict__ edge_W, const float* __restrict__ edge_g,
            float* __restrict__ out)
{
    extern __shared__ float sm[];
    float* wW1t = sm;             // [8][16]   128
    float* wb1  = wW1t + 128;     // 16
    float* wW2t = wb1  + 16;      // [16][32]  512
    float* wb2  = wW2t + 512;     // 32
    float* wAh  = wb2  + 32;      // [16][32]  512  folded (g*W1a)@W2, [c][o]
    float* wbf  = wAh  + 512;     // 32
    float* wBg  = wbf  + 32;      // [32][32]  1024 g*W1[:,32:], [c][o]
    float* wF2t = wBg  + 1024;    // [32][64]  2048
    float* wab  = wF2t + 2048;    // 64
    float* wWEt = wab  + 64;      // [64][64]  4096
    float* t_in = wWEt + 4096;    // [8][128]  1024
    float* t_h  = t_in + 1024;    // [16][RS]  2112
    float* t_rif= t_h  + 16*RS;   // [64][RS]  8448
    float* t_att= t_rif+ 64*RS;   // [32][RS]  4224
    int*   s_idx= (int*)(t_att + 32*RS);  // 128

    const int tid = threadIdx.x;
    const int w   = tid >> 5;
    const int l   = tid & 31;
    const int p0  = l*4;                  // GEMM1 layout
    const int b   = blockIdx.x >> 4;
    const int n0  = (blockIdx.x & 15) << 7;

    // new tiling coords
    const int ow   = w & 1;
    const int pw   = w >> 1;
    const int osub = l >> 2;
    const int psub = l & 3;
    const int pb   = pw*32 + psub*8;      // 8 points
    const int ob45 = ow*32 + osub*4;      // 4 o (GEMM4/5/gate/epi)
    const int ob23 = ow*16 + osub*2;      // 2 o (GEMM2/3)

    // ---- stage folded, transposed weights ----
    for (int i = tid; i < 128; i += 256) { int c=i>>4, o=i&15; wW1t[i] = dk_g1[o]*dk_W1[o*8+c]; }
    if (tid < 16) wb1[tid] = dk_g1[tid]*dk_b1[tid] + dk_be1[tid];
    for (int i = tid; i < 512; i += 256) { int c=i>>5, o=i&31; wW2t[i] = dk_W2[o*16+c]; }
    if (tid < 32) wb2[tid] = dk_b2[tid];
    for (int i = tid; i < 512; i += 256) {
        int c = i >> 5, o = i & 31;
        float s = 0.f;
        #pragma unroll
        for (int j = 0; j < 32; j++) s += ff_W1[o*64 + j] * dk_W2[j*16 + c];
        wAh[c*32 + o] = ff_g1[o] * s;
    }
    if (tid < 32) {
        float s = 0.f;
        #pragma unroll
        for (int j = 0; j < 32; j++) s += ff_W1[tid*64 + j] * dk_b2[j];
        wbf[tid] = ff_be1[tid] + ff_g1[tid] * s;
    }
    for (int i = tid; i < 1024; i += 256) { int c=i>>5, o=i&31; wBg[i] = ff_g1[o]*ff_W1[o*64+32+c]; }
    for (int i = tid; i < 2048; i += 256) { int c=i>>6, o=i&63; wF2t[i] = ff_W2[o*32+c]; }
    if (tid < 64) wab[tid] = act_b[tid];
    for (int i = tid; i < 4096; i += 256) { int c=i>>6, o=i&63; wWEt[i] = edge_g[o]*edge_W[o*128+c]; }
    // pre-stage appf(k=0)
    if (tid < 128) {
        const float* ap = appf + (((size_t)b*NN + n0 + tid)*NK + 0)*8;
        float4 a0 = *(const float4*)ap;
        float4 a1 = *(const float4*)(ap + 4);
        t_in[0*128+tid]=a0.x; t_in[1*128+tid]=a0.y; t_in[2*128+tid]=a0.z; t_in[3*128+tid]=a0.w;
        t_in[4*128+tid]=a1.x; t_in[5*128+tid]=a1.y; t_in[6*128+tid]=a1.z; t_in[7*128+tid]=a1.w;
    }
    __syncthreads();

    float mx[4][8];                       // [o][point]
    #pragma unroll
    for (int o = 0; o < 4; o++)
        #pragma unroll
        for (int e = 0; e < 8; e++) mx[o][e] = -1e30f;

    #pragma unroll 1
    for (int k = 0; k < NK; k++) {
        // ---- staging LDGs (glf + idx), STS deferred past GEMM1 ----
        float4 gl[4];
        int idxr = 0;
        {
            const float* src = g_glT + (((size_t)b*NK + k)*32)*NN + n0;
            #pragma unroll
            for (int u = 0; u < 4; u++) {
                int f = (tid + u*256)*4;
                int c = f >> 7, col = f & 127;
                gl[u] = *(const float4*)&src[c*NN + col];
            }
        }
        if (tid < 128) idxr = g_idxT[((size_t)b*NK + k)*NN + n0 + tid];

        // ---- GEMM1: dk1 [16x128], K=8 (old layout) ----
        {
            const int o0 = w*2;
            const u64 bias = *(const u64*)&wb1[o0];
            u64 a0 = bias, a1 = bias, a2 = bias, a3 = bias;
            #pragma unroll
            for (int c = 0; c < 8; c++) {
                u64 wv = *(const u64*)&wW1t[c*16 + o0];
                float4 bv = *(float4*)&t_in[c*128 + p0];
                ffma2(a0, wv, f2pack(bv.x, bv.x));
                ffma2(a1, wv, f2pack(bv.y, bv.y));
                ffma2(a2, wv, f2pack(bv.z, bv.z));
                ffma2(a3, wv, f2pack(bv.w, bv.w));
            }
            float l0,h0,l1,h1,l2,h2,l3,h3;
            f2unpack(a0,l0,h0); f2unpack(a1,l1,h1); f2unpack(a2,l2,h2); f2unpack(a3,l3,h3);
            *(float4*)&t_h[o0*RS + p0]     = make_float4(fmaxf(l0,0.f), fmaxf(l1,0.f), fmaxf(l2,0.f), fmaxf(l3,0.f));
            *(float4*)&t_h[(o0+1)*RS + p0] = make_float4(fmaxf(h0,0.f), fmaxf(h1,0.f), fmaxf(h2,0.f), fmaxf(h3,0.f));
        }
        // deferred STS: glf rows 32..63, idx
        {
            #pragma unroll
            for (int u = 0; u < 4; u++) {
                int f = (tid + u*256)*4;
                int c = f >> 7, col = f & 127;
                *(float4*)&t_rif[(32+c)*RS + col] = gl[u];
            }
        }
        if (tid < 128) s_idx[tid] = idxr;
        __syncthreads();   // A

        // ---- appf(k+1) LDG ----
        float4 a0n, a1n;
        if (tid < 128) {
            int kn = (k+1 < NK) ? k+1 : k;
            const float* ap = appf + (((size_t)b*NN + n0 + tid)*NK + kn)*8;
            a0n = *(const float4*)ap;
            a1n = *(const float4*)(ap + 4);
        }

        // ---- GEMM2: dk2 [32x128], K=16. lane 2o x 8p, point-pair acc ----
        {
            u64 b0 = f2pack(wb2[ob23],   wb2[ob23]);
            u64 b1 = f2pack(wb2[ob23+1], wb2[ob23+1]);
            u64 acc[2][4];
            #pragma unroll
            for (int pp = 0; pp < 4; pp++) { acc[0][pp] = b0; acc[1][pp] = b1; }
            #pragma unroll 4
            for (int c = 0; c < 16; c++) {
                float2 wv = *(const float2*)&wW2t[c*32 + ob23];
                u64 w0 = f2pack(wv.x, wv.x), w1 = f2pack(wv.y, wv.y);
                ulonglong2 B0 = *(const ulonglong2*)&t_h[c*RS + pb];
                ulonglong2 B1 = *(const ulonglong2*)&t_h[c*RS + pb + 4];
                ffma2(acc[0][0], w0, B0.x); ffma2(acc[1][0], w1, B0.x);
                ffma2(acc[0][1], w0, B0.y); ffma2(acc[1][1], w1, B0.y);
                ffma2(acc[0][2], w0, B1.x); ffma2(acc[1][2], w1, B1.x);
                ffma2(acc[0][3], w0, B1.y); ffma2(acc[1][3], w1, B1.y);
            }
            #pragma unroll
            for (int od = 0; od < 2; od++) {
                ulonglong2 s0, s1;
                s0.x = acc[od][0]; s0.y = acc[od][1];
                s1.x = acc[od][2]; s1.y = acc[od][3];
                *(ulonglong2*)&t_rif[(ob23+od)*RS + pb]     = s0;
                *(ulonglong2*)&t_rif[(ob23+od)*RS + pb + 4] = s1;
            }
        }
        // STS appf(k+1)
        if (tid < 128) {
            t_in[0*128+tid]=a0n.x; t_in[1*128+tid]=a0n.y; t_in[2*128+tid]=a0n.z; t_in[3*128+tid]=a0n.w;
            t_in[4*128+tid]=a1n.x; t_in[5*128+tid]=a1n.y; t_in[6*128+tid]=a1n.z; t_in[7*128+tid]=a1n.w;
        }
        // ---- GEMM3 (folded): att = wAh@h (16c) + wBg@glf (32c) + wbf; leaky ----
        {
            u64 b0 = f2pack(wbf[ob23],   wbf[ob23]);
            u64 b1 = f2pack(wbf[ob23+1], wbf[ob23+1]);
            u64 acc[2][4];
            #pragma unroll
            for (int pp = 0; pp < 4; pp++) { acc[0][pp] = b0; acc[1][pp] = b1; }
            #pragma unroll 4
            for (int c = 0; c < 16; c++) {
                float2 wv = *(const float2*)&wAh[c*32 + ob23];
                u64 w0 = f2pack(wv.x, wv.x), w1 = f2pack(wv.y, wv.y);
                ulonglong2 B0 = *(const ulonglong2*)&t_h[c*RS + pb];
                ulonglong2 B1 = *(const ulonglong2*)&t_h[c*RS + pb + 4];
                ffma2(acc[0][0], w0, B0.x); ffma2(acc[1][0], w1, B0.x);
                ffma2(acc[0][1], w0, B0.y); ffma2(acc[1][1], w1, B0.y);
                ffma2(acc[0][2], w0, B1.x); ffma2(acc[1][2], w1, B1.x);
                ffma2(acc[0][3], w0, B1.y); ffma2(acc[1][3], w1, B1.y);
            }
            #pragma unroll 4
            for (int c = 0; c < 32; c++) {
                float2 wv = *(const float2*)&wBg[c*32 + ob23];
                u64 w0 = f2pack(wv.x, wv.x), w1 = f2pack(wv.y, wv.y);
                ulonglong2 B0 = *(const ulonglong2*)&t_rif[(32+c)*RS + pb];
                ulonglong2 B1 = *(const ulonglong2*)&t_rif[(32+c)*RS + pb + 4];
                ffma2(acc[0][0], w0, B0.x); ffma2(acc[1][0], w1, B0.x);
                ffma2(acc[0][1], w0, B0.y); ffma2(acc[1][1], w1, B0.y);
                ffma2(acc[0][2], w0, B1.x); ffma2(acc[1][2], w1, B1.x);
                ffma2(acc[0][3], w0, B1.y); ffma2(acc[1][3], w1, B1.y);
            }
            #pragma unroll
            for (int od = 0; od < 2; od++) {
                float v0,v1,v2,v3,v4,v5,v6,v7;
                f2unpack(acc[od][0], v0, v1);
                f2unpack(acc[od][1], v2, v3);
                f2unpack(acc[od][2], v4, v5);
                f2unpack(acc[od][3], v6, v7);
                *(float4*)&t_att[(ob23+od)*RS + pb] =
                    make_float4(LEAKY(v0), LEAKY(v1), LEAKY(v2), LEAKY(v3));
                *(float4*)&t_att[(ob23+od)*RS + pb + 4] =
                    make_float4(LEAKY(v4), LEAKY(v5), LEAKY(v6), LEAKY(v7));
            }
        }
        __syncthreads();   // B

        // ---- GEMM4: ff2 [64x128], K=32; sigmoid; gate in place ----
        {
            u64 acc[4][4];
            #pragma unroll
            for (int o = 0; o < 4; o++)
                #pragma unroll
                for (int pp = 0; pp < 4; pp++) acc[o][pp] = 0ull;
            #pragma unroll 4
            for (int c = 0; c < 32; c++) {
                float4 wv = *(const float4*)&wF2t[c*64 + ob45];
                u64 w0 = f2pack(wv.x, wv.x), w1 = f2pack(wv.y, wv.y);
                u64 w2 = f2pack(wv.z, wv.z), w3 = f2pack(wv.w, wv.w);
                ulonglong2 B0 = *(const ulonglong2*)&t_att[c*RS + pb];
                ulonglong2 B1 = *(const ulonglong2*)&t_att[c*RS + pb + 4];
                ffma2(acc[0][0], w0, B0.x); ffma2(acc[1][0], w1, B0.x);
                ffma2(acc[2][0], w2, B0.x); ffma2(acc[3][0], w3, B0.x);
                ffma2(acc[0][1], w0, B0.y); ffma2(acc[1][1], w1, B0.y);
                ffma2(acc[2][1], w2, B0.y); ffma2(acc[3][1], w3, B0.y);
                ffma2(acc[0][2], w0, B1.x); ffma2(acc[1][2], w1, B1.x);
                ffma2(acc[2][2], w2, B1.x); ffma2(acc[3][2], w3, B1.x);
                ffma2(acc[0][3], w0, B1.y); ffma2(acc[1][3], w1, B1.y);
                ffma2(acc[2][3], w2, B1.y); ffma2(acc[3][3], w3, B1.y);
            }
            // gate, split in two o-halves to bound registers
            #pragma unroll
            for (int oh = 0; oh < 2; oh++) {
                float2 bx2[8];
                #pragma unroll
                for (int e = 0; e < 8; e++) {
                    int j = s_idx[pb + e];
                    bx2[e] = *(const float2*)&g_bxT[((size_t)b*NN + j)*64 + ob45 + 2*oh];
                }
                #pragma unroll
                for (int od = 0; od < 2; od++) {
                    const int o = 2*oh + od;
                    const int row = ob45 + o;
                    const float ab = wab[row];
                    ulonglong2 F0 = *(const ulonglong2*)&t_rif[row*RS + pb];
                    ulonglong2 F1 = *(const ulonglong2*)&t_rif[row*RS + pb + 4];
                    u64 fp[4] = {F0.x, F0.y, F1.x, F1.y};
                    float vout[8];
                    #pragma unroll
                    for (int pp = 0; pp < 4; pp++) {
                        float s0, s1, f0, f1;
                        f2unpack(acc[o][pp], s0, s1);
                        s0 = 1.f/(1.f + __expf(-s0));
                        s1 = 1.f/(1.f + __expf(-s1));
                        f2unpack(fp[pp], f0, f1);
                        float bx0 = (od == 0) ? bx2[2*pp].x   : bx2[2*pp].y;
                        float bx1 = (od == 0) ? bx2[2*pp+1].x : bx2[2*pp+1].y;
                        vout[2*pp]   = fmaxf(f0*s0*bx0 + ab, 0.f);
                        vout[2*pp+1] = fmaxf(f1*s1*bx1 + ab, 0.f);
                    }
                    *(float4*)&t_rif[row*RS + pb] =
                        make_float4(vout[0], vout[1], vout[2], vout[3]);
                    *(float4*)&t_rif[row*RS + pb + 4] =
                        make_float4(vout[4], vout[5], vout[6], vout[7]);
                }
            }
        }
        __syncthreads();   // C

        // ---- GEMM5: edge [64x128], K=64; running max ----
        {
            u64 acc[4][4];
            #pragma unroll
            for (int o = 0; o < 4; o++)
                #pragma unroll
                for (int pp = 0; pp < 4; pp++) acc[o][pp] = 0ull;
            #pragma unroll 4
            for (int c = 0; c < 64; c++) {
                float4 wv = *(const float4*)&wWEt[c*64 + ob45];
                u64 w0 = f2pack(wv.x, wv.x), w1 = f2pack(wv.y, wv.y);
                u64 w2 = f2pack(wv.z, wv.z), w3 = f2pack(wv.w, wv.w);
                ulonglong2 B0 = *(const ulonglong2*)&t_rif[c*RS + pb];
                ulonglong2 B1 = *(const ulonglong2*)&t_rif[c*RS + pb + 4];
                ffma2(acc[0][0], w0, B0.x); ffma2(acc[1][0], w1, B0.x);
                ffma2(acc[2][0], w2, B0.x); ffma2(acc[3][0], w3, B0.x);
                ffma2(acc[0][1], w0, B0.y); ffma2(acc[1][1], w1, B0.y);
                ffma2(acc[2][1], w2, B0.y); ffma2(acc[3][1], w3, B0.y);
                ffma2(acc[0][2], w0, B1.x); ffma2(acc[1][2], w1, B1.x);
                ffma2(acc[2][2], w2, B1.x); ffma2(acc[3][2], w3, B1.x);
                ffma2(acc[0][3], w0, B1.y); ffma2(acc[1][3], w1, B1.y);
                ffma2(acc[2][3], w2, B1.y); ffma2(acc[3][3], w3, B1.y);
            }
            #pragma unroll
            for (int o = 0; o < 4; o++) {
                #pragma unroll
                for (int pp = 0; pp < 4; pp++) {
                    float lo, hi;
                    f2unpack(acc[o][pp], lo, hi);
                    mx[o][2*pp]   = fmaxf(mx[o][2*pp],   lo);
                    mx[o][2*pp+1] = fmaxf(mx[o][2*pp+1], hi);
                }
            }
        }
        __syncthreads();   // D
    }

    // ---- epilogue: out = leaky(mx + cst) ----
    {
        float4 cq[8];
        #pragma unroll
        for (int e = 0; e < 8; e++)
            cq[e] = *(const float4*)&g_cst[((size_t)b*NN + n0 + pb + e)*64 + ob45];
        #pragma unroll
        for (int o = 0; o < 4; o++) {
            const int row = ob45 + o;
            float v[8];
            #pragma unroll
            for (int e = 0; e < 8; e++) {
                float cc = (o==0) ? cq[e].x : (o==1) ? cq[e].y : (o==2) ? cq[e].z : cq[e].w;
                v[e] = LEAKY(mx[o][e] + cc);
            }
            *(float4*)&out[((size_t)b*64 + row)*NN + n0 + pb]     = make_float4(v[0],v[1],v[2],v[3]);
            *(float4*)&out[((size_t)b*64 + row)*NN + n0 + pb + 4] = make_float4(v[4],v[5],v[6],v[7]);
        }
    }
}

// =====================================================================
extern "C" void kernel_launch(void* const* d_in, const int* in_sizes, int n_in,
                              void* d_out, int out_size)
{
    const float* pos     = (const float*)d_in[0];
    const float* x       = (const float*)d_in[1];
    const float* glf     = (const float*)d_in[2];
    const float* appf    = (const float*)d_in[3];
    const float* basis_W = (const float*)d_in[4];
    const float* dk_W1   = (const float*)d_in[5];
    const float* dk_b1   = (const float*)d_in[6];
    const float* dk_g1   = (const float*)d_in[7];
    const float* dk_be1  = (const float*)d_in[8];
    const float* dk_W2   = (const float*)d_in[9];
    const float* dk_b2   = (const float*)d_in[10];
    const float* act_g   = (const float*)d_in[11];
    const float* act_b   = (const float*)d_in[12];
    const float* ff_W1   = (const float*)d_in[13];
    const float* ff_g1   = (const float*)d_in[14];
    const float* ff_be1  = (const float*)d_in[15];
    const float* ff_W2   = (const float*)d_in[16];
    const float* edge_W  = (const float*)d_in[17];
    const float* edge_g  = (const float*)d_in[18];
    const float* edge_be = (const float*)d_in[19];
    float* out = (float*)d_out;

    knn_kernel<<<dim3(NN/32, NB), 256>>>(pos);
    prep_kernel<<<(NB*NN)/128, 128>>>(x, basis_W, edge_W, act_g, edge_g, edge_be);
    tr_kernel<<<dim3(NN/64, 32, NB), 256>>>(glf);

    const int smem_bytes = (8464 + 1024 + 16*RS + 64*RS + 32*RS + 128) * (int)sizeof(float);
    cudaFuncSetAttribute(main_kernel, cudaFuncAttributeMaxDynamicSharedMemorySize, smem_bytes);
    main_kernel<<<NB*NN/128, 256, smem_bytes>>>(appf,
                                                dk_W1, dk_b1, dk_g1, dk_be1,
                                                dk_W2, dk_b2, act_b,
                                                ff_W1, ff_g1, ff_be1, ff_W2,
                                                edge_W, edge_g, out);
}

// round 12
// speedup vs baseline: 1.0569x; 1.0569x over previous
#include <cuda_runtime.h>
#include <math.h>

#define NB 16
#define NN 2048
#define NK 20
#define NC 64

typedef unsigned long long u64;

// ---- scratch (static __device__, allocation-free) ----
__device__ int   g_idxT[NB*NK*NN];          // knn indices, [b][k][n]
__device__ float g_bxT [NB*NN*NC];          // act_g * (basis_W @ x), point-major [p][c]
__device__ float g_cst [NB*NN*NC];          // edge_g*((We2-We1)@x) + edge_be, [p][o]
__device__ float g_glT [NB*NK*32*NN];       // glf transposed to [b][k][c][n]

// ---- packed f32x2 helpers (Blackwell FFMA2) ----
__device__ __forceinline__ u64 f2pack(float lo, float hi) {
    u64 r; asm("mov.b64 %0, {%1, %2};" : "=l"(r) : "f"(lo), "f"(hi)); return r;
}
__device__ __forceinline__ void f2unpack(u64 v, float& lo, float& hi) {
    asm("mov.b64 {%0, %1}, %2;" : "=f"(lo), "=f"(hi) : "l"(v));
}
__device__ __forceinline__ void ffma2(u64& d, u64 a, u64 b) {
    asm("fma.rn.f32x2 %0, %1, %2, %3;" : "=l"(d) : "l"(a), "l"(b), "l"(d));
}

#define LEAKY(v) ((v) > 0.f ? (v) : 0.2f*(v))

// =====================================================================
// KNN, warp-cooperative, DUAL-QUERY interleaved: each warp runs two
// independent distributed top-20 lists at once; the two shfl/ballot
// insert chains interleave for 2x ILP on the latency-bound path.
// All control flow warp-uniform. Ties: ascending-m processing with
// strict > placement == lax.top_k. Self excluded via select.
// =====================================================================
__global__ void __launch_bounds__(256)
knn_kernel(const float* __restrict__ pos)
{
    __shared__ float4 sp[NN];
    const int b    = blockIdx.y;
    const int tid  = threadIdx.x;
    const int w    = tid >> 5;
    const int lane = tid & 31;
    const float* pb = pos + (size_t)b*3*NN;
    for (int m = tid; m < NN; m += 256) {
        float xx = pb[m], yy = pb[NN + m], zz = pb[2*NN + m];
        sp[m] = make_float4(xx, yy, zz, xx*xx + yy*yy + zz*zz);
    }
    __syncthreads();

    const int qbase = blockIdx.x*32 + w*4;
    #pragma unroll 1
    for (int qp = 0; qp < 2; qp++) {
        const int q0 = qbase + qp*2;
        const int q1 = q0 + 1;
        const float4 pq0 = sp[q0];
        const float4 pq1 = sp[q1];
        float v0 = -1e30f, v1 = -1e30f;
        int   i0 = 0,      i1 = 0;

        #pragma unroll 1
        for (int blk = 0; blk < NN; blk += 32) {
            const int m = blk + lane;
            float4 pm = sp[m];
            float pd0 = 2.0f*(pq0.x*pm.x + pq0.y*pm.y + pq0.z*pm.z) - pq0.w - pm.w;
            float pd1 = 2.0f*(pq1.x*pm.x + pq1.y*pm.y + pq1.z*pm.z) - pq1.w - pm.w;
            pd0 = (m == q0) ? -1e30f : pd0;
            pd1 = (m == q1) ? -1e30f : pd1;
            float t0 = __shfl_sync(0xFFFFFFFFu, v0, 19);
            float t1 = __shfl_sync(0xFFFFFFFFu, v1, 19);
            unsigned m0 = __ballot_sync(0xFFFFFFFFu, pd0 > t0);
            unsigned m1 = __ballot_sync(0xFFFFFFFFu, pd1 > t1);
            while (m0 | m1) {
                if (m0) {
                    int src = __ffs((int)m0) - 1;
                    float pdv = __shfl_sync(0xFFFFFFFFu, pd0, src);
                    m0 &= m0 - 1;
                    unsigned cmp = __ballot_sync(0xFFFFFFFFu, pdv > v0) & 0xFFFFFu;
                    if (cmp) {
                        int pos = __ffs((int)cmp) - 1;
                        float nv = __shfl_up_sync(0xFFFFFFFFu, v0, 1);
                        int  nid = __shfl_up_sync(0xFFFFFFFFu, i0, 1);
                        if (lane > pos)  { v0 = nv;  i0 = nid; }
                        if (lane == pos) { v0 = pdv; i0 = blk + src; }
                    }
                }
                if (m1) {
                    int src = __ffs((int)m1) - 1;
                    float pdv = __shfl_sync(0xFFFFFFFFu, pd1, src);
                    m1 &= m1 - 1;
                    unsigned cmp = __ballot_sync(0xFFFFFFFFu, pdv > v1) & 0xFFFFFu;
                    if (cmp) {
                        int pos = __ffs((int)cmp) - 1;
                        float nv = __shfl_up_sync(0xFFFFFFFFu, v1, 1);
                        int  nid = __shfl_up_sync(0xFFFFFFFFu, i1, 1);
                        if (lane > pos)  { v1 = nv;  i1 = nid; }
                        if (lane == pos) { v1 = pdv; i1 = blk + src; }
                    }
                }
            }
        }
        if (lane < NK) {
            g_idxT[((size_t)b*NK + lane)*NN + q0] = i0;
            g_idxT[((size_t)b*NK + lane)*NN + q1] = i1;
        }
    }
}

// =====================================================================
// prep (unchanged)
// =====================================================================
__global__ void prep_kernel(const float* __restrict__ x,
                            const float* __restrict__ basis_W,
                            const float* __restrict__ edge_W,
                            const float* __restrict__ act_g,
                            const float* __restrict__ edge_g,
                            const float* __restrict__ edge_be)
{
    __shared__ float sB[64*64];
    __shared__ float sD[64*64];
    __shared__ float sag[64], seg[64], seb[64];
    const int tid = threadIdx.x;
    for (int i = tid; i < 4096; i += blockDim.x) {
        sB[i] = basis_W[i];
        int o = i >> 6, c = i & 63;
        sD[i] = edge_W[o*128 + 64 + c] - edge_W[o*128 + c];
    }
    for (int i = tid; i < 64; i += blockDim.x) {
        sag[i] = act_g[i]; seg[i] = edge_g[i]; seb[i] = edge_be[i];
    }
    __syncthreads();

    const int p = blockIdx.x * blockDim.x + tid;
    const int b = p / NN, n = p % NN;
    const float* xp = x + (size_t)b*64*NN + n;
    float xv[64];
    #pragma unroll
    for (int c = 0; c < 64; c++) xv[c] = xp[(size_t)c*NN];

    float* bo = g_bxT + (size_t)p*64;
    #pragma unroll 4
    for (int o = 0; o < 64; o++) {
        float acc = 0.f;
        #pragma unroll
        for (int c = 0; c < 64; c++) acc += sB[o*64+c]*xv[c];
        bo[o] = acc * sag[o];
    }
    float* co = g_cst + (size_t)p*64;
    #pragma unroll 4
    for (int o = 0; o < 64; o++) {
        float acc = 0.f;
        #pragma unroll
        for (int c = 0; c < 64; c++) acc += sD[o*64+c]*xv[c];
        co[o] = acc*seg[o] + seb[o];
    }
}

// =====================================================================
// glf transpose (unchanged)
// =====================================================================
__global__ void tr_kernel(const float* __restrict__ glf)
{
    __shared__ float s[64*21];
    const int n0 = blockIdx.x * 64;
    const int c  = blockIdx.y;
    const int b  = blockIdx.z;
    const int tid = threadIdx.x;
    const float* in = glf + (((size_t)b*32 + c)*NN + n0) * NK;
    #pragma unroll
    for (int u = 0; u < 5; u++) {
        int f = tid + u*256;
        int n = f / 20, k = f % 20;
        s[n*21 + k] = in[f];
    }
    __syncthreads();
    #pragma unroll
    for (int u = 0; u < 5; u++) {
        int f = tid + u*256;
        int k = f >> 6, n = f & 63;
        g_glT[(((size_t)b*NK + k)*32 + c)*NN + n0 + n] = s[n*21 + k];
    }
}

// =====================================================================
// main fused kernel (round-10 best: 337us): 256 thr, 128-pt tile,
// 4 pts/thread, dk2-into-ff1 fold, deferred STS, appf pipelining.
// =====================================================================
__global__ void __launch_bounds__(256, 2)
main_kernel(const float* __restrict__ appf,
            const float* __restrict__ dk_W1, const float* __restrict__ dk_b1,
            const float* __restrict__ dk_g1, const float* __restrict__ dk_be1,
            const float* __restrict__ dk_W2, const float* __restrict__ dk_b2,
            const float* __restrict__ act_b,
            const float* __restrict__ ff_W1, const float* __restrict__ ff_g1,
            const float* __restrict__ ff_be1, const float* __restrict__ ff_W2,
            const float* __restrict__ edge_W, const float* __restrict__ edge_g,
            float* __restrict__ out)
{
    extern __shared__ float sm[];
    float* wW1t = sm;             // [8][16]   128
    float* wb1  = wW1t + 128;     // 16
    float* wW2t = wb1  + 16;      // [16][32]  512
    float* wb2  = wW2t + 512;     // 32
    float* wAh  = wb2  + 32;      // [16][32]  512  folded (g*W1a)@W2, [c][o]
    float* wbf  = wAh  + 512;     // 32
    float* wBg  = wbf  + 32;      // [32][32]  1024 g*W1[:,32:], [c][o]
    float* wF2t = wBg  + 1024;    // [32][64]  2048
    float* wab  = wF2t + 2048;    // 64
    float* wWEt = wab  + 64;      // [64][64]  4096
    float* t_in = wWEt + 4096;    // [8][128]  1024
    float* t_h  = t_in + 1024;    // [16][128] 2048
    float* t_rif= t_h  + 2048;    // [64][128] 8192
    float* t_att= t_rif+ 8192;    // [32][128] 4096
    int*   s_idx= (int*)(t_att + 4096);   // 128

    const int tid = threadIdx.x;
    const int w   = tid >> 5;
    const int l   = tid & 31;
    const int p0  = l*4;
    const int b   = blockIdx.x >> 4;
    const int n0  = (blockIdx.x & 15) << 7;

    for (int i = tid; i < 128; i += 256) { int c=i>>4, o=i&15; wW1t[i] = dk_g1[o]*dk_W1[o*8+c]; }
    if (tid < 16) wb1[tid] = dk_g1[tid]*dk_b1[tid] + dk_be1[tid];
    for (int i = tid; i < 512; i += 256) { int c=i>>5, o=i&31; wW2t[i] = dk_W2[o*16+c]; }
    if (tid < 32) wb2[tid] = dk_b2[tid];
    for (int i = tid; i < 512; i += 256) {
        int c = i >> 5, o = i & 31;
        float s = 0.f;
        #pragma unroll
        for (int j = 0; j < 32; j++) s += ff_W1[o*64 + j] * dk_W2[j*16 + c];
        wAh[c*32 + o] = ff_g1[o] * s;
    }
    if (tid < 32) {
        float s = 0.f;
        #pragma unroll
        for (int j = 0; j < 32; j++) s += ff_W1[tid*64 + j] * dk_b2[j];
        wbf[tid] = ff_be1[tid] + ff_g1[tid] * s;
    }
    for (int i = tid; i < 1024; i += 256) { int c=i>>5, o=i&31; wBg[i] = ff_g1[o]*ff_W1[o*64+32+c]; }
    for (int i = tid; i < 2048; i += 256) { int c=i>>6, o=i&63; wF2t[i] = ff_W2[o*32+c]; }
    if (tid < 64) wab[tid] = act_b[tid];
    for (int i = tid; i < 4096; i += 256) { int c=i>>6, o=i&63; wWEt[i] = edge_g[o]*edge_W[o*128+c]; }
    if (tid < 128) {
        const float* ap = appf + (((size_t)b*NN + n0 + tid)*NK + 0)*8;
        float4 a0 = *(const float4*)ap;
        float4 a1 = *(const float4*)(ap + 4);
        t_in[0*128+tid]=a0.x; t_in[1*128+tid]=a0.y; t_in[2*128+tid]=a0.z; t_in[3*128+tid]=a0.w;
        t_in[4*128+tid]=a1.x; t_in[5*128+tid]=a1.y; t_in[6*128+tid]=a1.z; t_in[7*128+tid]=a1.w;
    }
    __syncthreads();

    float mx[4][8];
    #pragma unroll
    for (int pp = 0; pp < 4; pp++)
        #pragma unroll
        for (int oo = 0; oo < 8; oo++) mx[pp][oo] = -1e30f;

    #pragma unroll 1
    for (int k = 0; k < NK; k++) {
        float4 gl[4];
        int idxr = 0;
        {
            const float* src = g_glT + (((size_t)b*NK + k)*32)*NN + n0;
            #pragma unroll
            for (int u = 0; u < 4; u++) {
                int f = (tid + u*256)*4;
                int c = f >> 7, col = f & 127;
                gl[u] = *(const float4*)&src[c*NN + col];
            }
        }
        if (tid < 128) idxr = g_idxT[((size_t)b*NK + k)*NN + n0 + tid];

        // GEMM1: dk1 [16x128], K=8
        {
            const int o0 = w*2;
            const u64 bias = *(const u64*)&wb1[o0];
            u64 a0 = bias, a1 = bias, a2 = bias, a3 = bias;
            #pragma unroll
            for (int c = 0; c < 8; c++) {
                u64 wv = *(const u64*)&wW1t[c*16 + o0];
                float4 bv = *(float4*)&t_in[c*128 + p0];
                ffma2(a0, wv, f2pack(bv.x, bv.x));
                ffma2(a1, wv, f2pack(bv.y, bv.y));
                ffma2(a2, wv, f2pack(bv.z, bv.z));
                ffma2(a3, wv, f2pack(bv.w, bv.w));
            }
            float l0,h0,l1,h1,l2,h2,l3,h3;
            f2unpack(a0,l0,h0); f2unpack(a1,l1,h1); f2unpack(a2,l2,h2); f2unpack(a3,l3,h3);
            *(float4*)&t_h[o0*128 + p0]     = make_float4(fmaxf(l0,0.f), fmaxf(l1,0.f), fmaxf(l2,0.f), fmaxf(l3,0.f));
            *(float4*)&t_h[(o0+1)*128 + p0] = make_float4(fmaxf(h0,0.f), fmaxf(h1,0.f), fmaxf(h2,0.f), fmaxf(h3,0.f));
        }
        {
            #pragma unroll
            for (int u = 0; u < 4; u++) {
                int f = (tid + u*256)*4;
                int c = f >> 7, col = f & 127;
                *(float4*)&t_rif[(32+c)*128 + col] = gl[u];
            }
        }
        if (tid < 128) s_idx[tid] = idxr;
        __syncthreads();   // A

        float4 a0n, a1n;
        if (tid < 128) {
            int kn = (k+1 < NK) ? k+1 : k;
            const float* ap = appf + (((size_t)b*NN + n0 + tid)*NK + kn)*8;
            a0n = *(const float4*)ap;
            a1n = *(const float4*)(ap + 4);
        }

        // GEMM2: dk2 [32x128], K=16
        {
            const int o0 = w*4;
            ulonglong2 bi = *(const ulonglong2*)&wb2[o0];
            u64 acc[4][2];
            #pragma unroll
            for (int pp = 0; pp < 4; pp++) { acc[pp][0] = bi.x; acc[pp][1] = bi.y; }
            #pragma unroll
            for (int c = 0; c < 16; c++) {
                ulonglong2 wv = *(const ulonglong2*)&wW2t[c*32 + o0];
                float4 bv = *(float4*)&t_h[c*128 + p0];
                u64 bx = f2pack(bv.x,bv.x), by = f2pack(bv.y,bv.y);
                u64 bz = f2pack(bv.z,bv.z), bw = f2pack(bv.w,bv.w);
                ffma2(acc[0][0], wv.x, bx); ffma2(acc[0][1], wv.y, bx);
                ffma2(acc[1][0], wv.x, by); ffma2(acc[1][1], wv.y, by);
                ffma2(acc[2][0], wv.x, bz); ffma2(acc[2][1], wv.y, bz);
                ffma2(acc[3][0], wv.x, bw); ffma2(acc[3][1], wv.y, bw);
            }
            #pragma unroll
            for (int pr = 0; pr < 2; pr++) {
                float l0,h0,l1,h1,l2,h2,l3,h3;
                f2unpack(acc[0][pr],l0,h0); f2unpack(acc[1][pr],l1,h1);
                f2unpack(acc[2][pr],l2,h2); f2unpack(acc[3][pr],l3,h3);
                *(float4*)&t_rif[(o0+2*pr)*128 + p0]   = make_float4(l0,l1,l2,l3);
                *(float4*)&t_rif[(o0+2*pr+1)*128 + p0] = make_float4(h0,h1,h2,h3);
            }
        }
        if (tid < 128) {
            t_in[0*128+tid]=a0n.x; t_in[1*128+tid]=a0n.y; t_in[2*128+tid]=a0n.z; t_in[3*128+tid]=a0n.w;
            t_in[4*128+tid]=a1n.x; t_in[5*128+tid]=a1n.y; t_in[6*128+tid]=a1n.z; t_in[7*128+tid]=a1n.w;
        }
        // GEMM3 (folded): att = wAh@h (16c) + wBg@glf (32c) + wbf
        {
            const int o0 = w*4;
            ulonglong2 bi = *(const ulonglong2*)&wbf[o0];
            u64 acc[4][2];
            #pragma unroll
            for (int pp = 0; pp < 4; pp++) { acc[pp][0] = bi.x; acc[pp][1] = bi.y; }
            #pragma unroll 4
            for (int c = 0; c < 16; c++) {
                ulonglong2 wv = *(const ulonglong2*)&wAh[c*32 + o0];
                float4 bv = *(float4*)&t_h[c*128 + p0];
                u64 bx = f2pack(bv.x,bv.x), by = f2pack(bv.y,bv.y);
                u64 bz = f2pack(bv.z,bv.z), bw = f2pack(bv.w,bv.w);
                ffma2(acc[0][0], wv.x, bx); ffma2(acc[0][1], wv.y, bx);
                ffma2(acc[1][0], wv.x, by); ffma2(acc[1][1], wv.y, by);
                ffma2(acc[2][0], wv.x, bz); ffma2(acc[2][1], wv.y, bz);
                ffma2(acc[3][0], wv.x, bw); ffma2(acc[3][1], wv.y, bw);
            }
            #pragma unroll 4
            for (int c = 0; c < 32; c++) {
                ulonglong2 wv = *(const ulonglong2*)&wBg[c*32 + o0];
                float4 bv = *(float4*)&t_rif[(32+c)*128 + p0];
                u64 bx = f2pack(bv.x,bv.x), by = f2pack(bv.y,bv.y);
                u64 bz = f2pack(bv.z,bv.z), bw = f2pack(bv.w,bv.w);
                ffma2(acc[0][0], wv.x, bx); ffma2(acc[0][1], wv.y, bx);
                ffma2(acc[1][0], wv.x, by); ffma2(acc[1][1], wv.y, by);
                ffma2(acc[2][0], wv.x, bz); ffma2(acc[2][1], wv.y, bz);
                ffma2(acc[3][0], wv.x, bw); ffma2(acc[3][1], wv.y, bw);
            }
            #pragma unroll
            for (int pr = 0; pr < 2; pr++) {
                float l0,h0,l1,h1,l2,h2,l3,h3;
                f2unpack(acc[0][pr],l0,h0); f2unpack(acc[1][pr],l1,h1);
                f2unpack(acc[2][pr],l2,h2); f2unpack(acc[3][pr],l3,h3);
                *(float4*)&t_att[(o0+2*pr)*128 + p0] =
                    make_float4(LEAKY(l0),LEAKY(l1),LEAKY(l2),LEAKY(l3));
                *(float4*)&t_att[(o0+2*pr+1)*128 + p0] =
                    make_float4(LEAKY(h0),LEAKY(h1),LEAKY(h2),LEAKY(h3));
            }
        }
        __syncthreads();   // B

        // GEMM4: ff2 [64x128], K=32; sigmoid; gate in place
        {
            const int o0 = w*8;
            u64 acc[4][4];
            #pragma unroll
            for (int pp = 0; pp < 4; pp++)
                #pragma unroll
                for (int pr = 0; pr < 4; pr++) acc[pp][pr] = 0ull;
            #pragma unroll 4
            for (int c = 0; c < 32; c++) {
                ulonglong2 wA = *(const ulonglong2*)&wF2t[c*64 + o0];
                ulonglong2 wB = *(const ulonglong2*)&wF2t[c*64 + o0 + 4];
                float4 bv = *(float4*)&t_att[c*128 + p0];
                u64 bx = f2pack(bv.x,bv.x), by = f2pack(bv.y,bv.y);
                u64 bz = f2pack(bv.z,bv.z), bw = f2pack(bv.w,bv.w);
                ffma2(acc[0][0], wA.x, bx); ffma2(acc[0][1], wA.y, bx);
                ffma2(acc[0][2], wB.x, bx); ffma2(acc[0][3], wB.y, bx);
                ffma2(acc[1][0], wA.x, by); ffma2(acc[1][1], wA.y, by);
                ffma2(acc[1][2], wB.x, by); ffma2(acc[1][3], wB.y, by);
                ffma2(acc[2][0], wA.x, bz); ffma2(acc[2][1], wA.y, bz);
                ffma2(acc[2][2], wB.x, bz); ffma2(acc[2][3], wB.y, bz);
                ffma2(acc[3][0], wA.x, bw); ffma2(acc[3][1], wA.y, bw);
                ffma2(acc[3][2], wB.x, bw); ffma2(acc[3][3], wB.y, bw);
            }
            #pragma unroll
            for (int hh = 0; hh < 2; hh++) {
                float sg[4][4];
                float bxv[4][4];
                #pragma unroll
                for (int pp = 0; pp < 4; pp++) {
                    float lo, hi;
                    f2unpack(acc[pp][2*hh],   lo, hi);
                    sg[pp][0] = 1.f/(1.f + __expf(-lo));
                    sg[pp][1] = 1.f/(1.f + __expf(-hi));
                    f2unpack(acc[pp][2*hh+1], lo, hi);
                    sg[pp][2] = 1.f/(1.f + __expf(-lo));
                    sg[pp][3] = 1.f/(1.f + __expf(-hi));
                    int j = s_idx[p0 + pp];
                    float4 gv = *(const float4*)(g_bxT + ((size_t)b*NN + j)*64 + o0 + 4*hh);
                    bxv[pp][0] = gv.x; bxv[pp][1] = gv.y; bxv[pp][2] = gv.z; bxv[pp][3] = gv.w;
                }
                #pragma unroll
                for (int oo = 0; oo < 4; oo++) {
                    int row = o0 + 4*hh + oo;
                    float ab = wab[row];
                    float4 rv = *(float4*)&t_rif[row*128 + p0];
                    rv.x = fmaxf(rv.x * sg[0][oo] * bxv[0][oo] + ab, 0.f);
                    rv.y = fmaxf(rv.y * sg[1][oo] * bxv[1][oo] + ab, 0.f);
                    rv.z = fmaxf(rv.z * sg[2][oo] * bxv[2][oo] + ab, 0.f);
                    rv.w = fmaxf(rv.w * sg[3][oo] * bxv[3][oo] + ab, 0.f);
                    *(float4*)&t_rif[row*128 + p0] = rv;
                }
            }
        }
        __syncthreads();   // C

        // GEMM5: edge [64x128], K=64; running max
        {
            const int o0 = w*8;
            u64 acc[4][4];
            #pragma unroll
            for (int pp = 0; pp < 4; pp++)
                #pragma unroll
                for (int pr = 0; pr < 4; pr++) acc[pp][pr] = 0ull;
            #pragma unroll 4
            for (int c = 0; c < 64; c++) {
                ulonglong2 wA = *(const ulonglong2*)&wWEt[c*64 + o0];
                ulonglong2 wB = *(const ulonglong2*)&wWEt[c*64 + o0 + 4];
                float4 bv = *(float4*)&t_rif[c*128 + p0];
                u64 bx = f2pack(bv.x,bv.x), by = f2pack(bv.y,bv.y);
                u64 bz = f2pack(bv.z,bv.z), bw = f2pack(bv.w,bv.w);
                ffma2(acc[0][0], wA.x, bx); ffma2(acc[0][1], wA.y, bx);
                ffma2(acc[0][2], wB.x, bx); ffma2(acc[0][3], wB.y, bx);
                ffma2(acc[1][0], wA.x, by); ffma2(acc[1][1], wA.y, by);
                ffma2(acc[1][2], wB.x, by); ffma2(acc[1][3], wB.y, by);
                ffma2(acc[2][0], wA.x, bz); ffma2(acc[2][1], wA.y, bz);
                ffma2(acc[2][2], wB.x, bz); ffma2(acc[2][3], wB.y, bz);
                ffma2(acc[3][0], wA.x, bw); ffma2(acc[3][1], wA.y, bw);
                ffma2(acc[3][2], wB.x, bw); ffma2(acc[3][3], wB.y, bw);
            }
            #pragma unroll
            for (int pp = 0; pp < 4; pp++) {
                #pragma unroll
                for (int pr = 0; pr < 4; pr++) {
                    float lo, hi;
                    f2unpack(acc[pp][pr], lo, hi);
                    mx[pp][2*pr]   = fmaxf(mx[pp][2*pr],   lo);
                    mx[pp][2*pr+1] = fmaxf(mx[pp][2*pr+1], hi);
                }
            }
        }
        __syncthreads();   // D
    }

    // epilogue: out = leaky(mx + cst)
    {
        const int o0 = w*8;
        #pragma unroll
        for (int hh = 0; hh < 2; hh++) {
            float cc[4][4];
            #pragma unroll
            for (int pp = 0; pp < 4; pp++) {
                float4 cv = *(const float4*)(g_cst + ((size_t)b*NN + n0 + p0 + pp)*64 + o0 + 4*hh);
                cc[pp][0]=cv.x; cc[pp][1]=cv.y; cc[pp][2]=cv.z; cc[pp][3]=cv.w;
            }
            #pragma unroll
            for (int oo = 0; oo < 4; oo++) {
                int row = o0 + 4*hh + oo;
                float4 v;
                v.x = LEAKY(mx[0][4*hh+oo] + cc[0][oo]);
                v.y = LEAKY(mx[1][4*hh+oo] + cc[1][oo]);
                v.z = LEAKY(mx[2][4*hh+oo] + cc[2][oo]);
                v.w = LEAKY(mx[3][4*hh+oo] + cc[3][oo]);
                *(float4*)&out[((size_t)b*64 + row)*NN + n0 + p0] = v;
            }
        }
    }
}

// =====================================================================
extern "C" void kernel_launch(void* const* d_in, const int* in_sizes, int n_in,
                              void* d_out, int out_size)
{
    const float* pos     = (const float*)d_in[0];
    const float* x       = (const float*)d_in[1];
    const float* glf     = (const float*)d_in[2];
    const float* appf    = (const float*)d_in[3];
    const float* basis_W = (const float*)d_in[4];
    const float* dk_W1   = (const float*)d_in[5];
    const float* dk_b1   = (const float*)d_in[6];
    const float* dk_g1   = (const float*)d_in[7];
    const float* dk_be1  = (const float*)d_in[8];
    const float* dk_W2   = (const float*)d_in[9];
    const float* dk_b2   = (const float*)d_in[10];
    const float* act_g   = (const float*)d_in[11];
    const float* act_b   = (const float*)d_in[12];
    const float* ff_W1   = (const float*)d_in[13];
    const float* ff_g1   = (const float*)d_in[14];
    const float* ff_be1  = (const float*)d_in[15];
    const float* ff_W2   = (const float*)d_in[16];
    const float* edge_W  = (const float*)d_in[17];
    const float* edge_g  = (const float*)d_in[18];
    const float* edge_be = (const float*)d_in[19];
    float* out = (float*)d_out;

    knn_kernel<<<dim3(NN/32, NB), 256>>>(pos);
    prep_kernel<<<(NB*NN)/128, 128>>>(x, basis_W, edge_W, act_g, edge_g, edge_be);
    tr_kernel<<<dim3(NN/64, 32, NB), 256>>>(glf);

    const int smem_bytes = (128+16+512+32+512+32+1024+2048+64+4096 + 1024+2048+8192+4096 + 128) * (int)sizeof(float);
    cudaFuncSetAttribute(main_kernel, cudaFuncAttributeMaxDynamicSharedMemorySize, smem_bytes);
    main_kernel<<<NB*NN/128, 256, smem_bytes>>>(appf,
                                                dk_W1, dk_b1, dk_g1, dk_be1,
                                                dk_W2, dk_b2, act_b,
                                                ff_W1, ff_g1, ff_be1, ff_W2,
                                                edge_W, edge_g, out);
}

// round 13
// speedup vs baseline: 1.0586x; 1.0016x over previous
#include <cuda_runtime.h>
#include <math.h>

#define NB 16
#define NN 2048
#define NK 20
#define NC 64

typedef unsigned long long u64;

// ---- scratch (static __device__, allocation-free) ----
__device__ int   g_idxT[NB*NK*NN];          // knn indices, [b][k][n]
__device__ float g_bxT [NB*NN*NC];          // act_g * (basis_W @ x), point-major [p][c]
__device__ float g_cst [NB*NN*NC];          // edge_g*((We2-We1)@x) + edge_be, [p][o]
__device__ float g_glT [NB*NK*32*NN];       // glf transposed to [b][k][c][n]

// ---- packed f32x2 helpers (Blackwell FFMA2) ----
__device__ __forceinline__ u64 f2pack(float lo, float hi) {
    u64 r; asm("mov.b64 %0, {%1, %2};" : "=l"(r) : "f"(lo), "f"(hi)); return r;
}
__device__ __forceinline__ void f2unpack(u64 v, float& lo, float& hi) {
    asm("mov.b64 {%0, %1}, %2;" : "=f"(lo), "=f"(hi) : "l"(v));
}
__device__ __forceinline__ void ffma2(u64& d, u64 a, u64 b) {
    asm("fma.rn.f32x2 %0, %1, %2, %3;" : "=l"(d) : "l"(a), "l"(b), "l"(d));
}

#define LEAKY(v) ((v) > 0.f ? (v) : 0.2f*(v))

// =====================================================================
// KNN, warp-cooperative, 64-wide candidate blocks: one t20 shfl + two
// ballots cover 64 candidates (halves fixed sync-op overhead vs 32-wide).
// Top-20 list distributed across lanes 0..19 (sorted descending); all
// control flow warp-uniform. Ties: [blk,blk+32) processed before
// [blk+32,blk+64), each ascending-src, strict > placement == lax.top_k.
// Self excluded via select (reference's dropped top-1 is self, pd=0).
// The if(cmp) guard makes correctness independent of stale ballot masks.
// =====================================================================
__global__ void __launch_bounds__(256)
knn_kernel(const float* __restrict__ pos)
{
    __shared__ float4 sp[NN];
    const int b    = blockIdx.y;
    const int tid  = threadIdx.x;
    const int w    = tid >> 5;
    const int lane = tid & 31;
    const float* pb = pos + (size_t)b*3*NN;
    for (int m = tid; m < NN; m += 256) {
        float xx = pb[m], yy = pb[NN + m], zz = pb[2*NN + m];
        sp[m] = make_float4(xx, yy, zz, xx*xx + yy*yy + zz*zz);
    }
    __syncthreads();

    const int qbase = blockIdx.x*32 + w*4;
    #pragma unroll 1
    for (int qi = 0; qi < 4; qi++) {
        const int q = qbase + qi;
        const float4 pq = sp[q];
        float v = -1e30f;        // lane's list slot (lanes 0..19 valid)
        int   idx = 0;

        #pragma unroll 1
        for (int blk = 0; blk < NN; blk += 64) {
            const int mA = blk + lane;
            const int mB = blk + 32 + lane;
            float4 pa = sp[mA];
            float4 pc = sp[mB];
            float pdA = 2.0f*(pq.x*pa.x + pq.y*pa.y + pq.z*pa.z) - pq.w - pa.w;
            float pdB = 2.0f*(pq.x*pc.x + pq.y*pc.y + pq.z*pc.z) - pq.w - pc.w;
            pdA = (mA == q) ? -1e30f : pdA;
            pdB = (mB == q) ? -1e30f : pdB;
            float t20 = __shfl_sync(0xFFFFFFFFu, v, 19);
            unsigned Ma = __ballot_sync(0xFFFFFFFFu, pdA > t20);
            unsigned Mb = __ballot_sync(0xFFFFFFFFu, pdB > t20);
            while (Ma) {
                int src = __ffs((int)Ma) - 1;
                float pdv = __shfl_sync(0xFFFFFFFFu, pdA, src);
                Ma &= Ma - 1;
                unsigned cmp = __ballot_sync(0xFFFFFFFFu, pdv > v) & 0xFFFFFu;
                if (cmp) {
                    int pos = __ffs((int)cmp) - 1;
                    float nv = __shfl_up_sync(0xFFFFFFFFu, v, 1);
                    int  nid = __shfl_up_sync(0xFFFFFFFFu, idx, 1);
                    if (lane > pos)  { v = nv;  idx = nid; }
                    if (lane == pos) { v = pdv; idx = blk + src; }
                }
            }
            while (Mb) {
                int src = __ffs((int)Mb) - 1;
                float pdv = __shfl_sync(0xFFFFFFFFu, pdB, src);
                Mb &= Mb - 1;
                unsigned cmp = __ballot_sync(0xFFFFFFFFu, pdv > v) & 0xFFFFFu;
                if (cmp) {
                    int pos = __ffs((int)cmp) - 1;
                    float nv = __shfl_up_sync(0xFFFFFFFFu, v, 1);
                    int  nid = __shfl_up_sync(0xFFFFFFFFu, idx, 1);
                    if (lane > pos)  { v = nv;  idx = nid; }
                    if (lane == pos) { v = pdv; idx = blk + 32 + src; }
                }
            }
        }
        if (lane < NK)
            g_idxT[((size_t)b*NK + lane)*NN + q] = idx;
    }
}

// =====================================================================
// prep (unchanged)
// =====================================================================
__global__ void prep_kernel(const float* __restrict__ x,
                            const float* __restrict__ basis_W,
                            const float* __restrict__ edge_W,
                            const float* __restrict__ act_g,
                            const float* __restrict__ edge_g,
                            const float* __restrict__ edge_be)
{
    __shared__ float sB[64*64];
    __shared__ float sD[64*64];
    __shared__ float sag[64], seg[64], seb[64];
    const int tid = threadIdx.x;
    for (int i = tid; i < 4096; i += blockDim.x) {
        sB[i] = basis_W[i];
        int o = i >> 6, c = i & 63;
        sD[i] = edge_W[o*128 + 64 + c] - edge_W[o*128 + c];
    }
    for (int i = tid; i < 64; i += blockDim.x) {
        sag[i] = act_g[i]; seg[i] = edge_g[i]; seb[i] = edge_be[i];
    }
    __syncthreads();

    const int p = blockIdx.x * blockDim.x + tid;
    const int b = p / NN, n = p % NN;
    const float* xp = x + (size_t)b*64*NN + n;
    float xv[64];
    #pragma unroll
    for (int c = 0; c < 64; c++) xv[c] = xp[(size_t)c*NN];

    float* bo = g_bxT + (size_t)p*64;
    #pragma unroll 4
    for (int o = 0; o < 64; o++) {
        float acc = 0.f;
        #pragma unroll
        for (int c = 0; c < 64; c++) acc += sB[o*64+c]*xv[c];
        bo[o] = acc * sag[o];
    }
    float* co = g_cst + (size_t)p*64;
    #pragma unroll 4
    for (int o = 0; o < 64; o++) {
        float acc = 0.f;
        #pragma unroll
        for (int c = 0; c < 64; c++) acc += sD[o*64+c]*xv[c];
        co[o] = acc*seg[o] + seb[o];
    }
}

// =====================================================================
// glf transpose (unchanged)
// =====================================================================
__global__ void tr_kernel(const float* __restrict__ glf)
{
    __shared__ float s[64*21];
    const int n0 = blockIdx.x * 64;
    const int c  = blockIdx.y;
    const int b  = blockIdx.z;
    const int tid = threadIdx.x;
    const float* in = glf + (((size_t)b*32 + c)*NN + n0) * NK;
    #pragma unroll
    for (int u = 0; u < 5; u++) {
        int f = tid + u*256;
        int n = f / 20, k = f % 20;
        s[n*21 + k] = in[f];
    }
    __syncthreads();
    #pragma unroll
    for (int u = 0; u < 5; u++) {
        int f = tid + u*256;
        int k = f >> 6, n = f & 63;
        g_glT[(((size_t)b*NK + k)*32 + c)*NN + n0 + n] = s[n*21 + k];
    }
}

// =====================================================================
// main fused kernel (round-10 best: 337us): 256 thr, 128-pt tile,
// 4 pts/thread, dk2-into-ff1 fold, deferred STS, appf pipelining.
// =====================================================================
__global__ void __launch_bounds__(256, 2)
main_kernel(const float* __restrict__ appf,
            const float* __restrict__ dk_W1, const float* __restrict__ dk_b1,
            const float* __restrict__ dk_g1, const float* __restrict__ dk_be1,
            const float* __restrict__ dk_W2, const float* __restrict__ dk_b2,
            const float* __restrict__ act_b,
            const float* __restrict__ ff_W1, const float* __restrict__ ff_g1,
            const float* __restrict__ ff_be1, const float* __restrict__ ff_W2,
            const float* __restrict__ edge_W, const float* __restrict__ edge_g,
            float* __restrict__ out)
{
    extern __shared__ float sm[];
    float* wW1t = sm;             // [8][16]   128
    float* wb1  = wW1t + 128;     // 16
    float* wW2t = wb1  + 16;      // [16][32]  512
    float* wb2  = wW2t + 512;     // 32
    float* wAh  = wb2  + 32;      // [16][32]  512  folded (g*W1a)@W2, [c][o]
    float* wbf  = wAh  + 512;     // 32
    float* wBg  = wbf  + 32;      // [32][32]  1024 g*W1[:,32:], [c][o]
    float* wF2t = wBg  + 1024;    // [32][64]  2048
    float* wab  = wF2t + 2048;    // 64
    float* wWEt = wab  + 64;      // [64][64]  4096
    float* t_in = wWEt + 4096;    // [8][128]  1024
    float* t_h  = t_in + 1024;    // [16][128] 2048
    float* t_rif= t_h  + 2048;    // [64][128] 8192
    float* t_att= t_rif+ 8192;    // [32][128] 4096
    int*   s_idx= (int*)(t_att + 4096);   // 128

    const int tid = threadIdx.x;
    const int w   = tid >> 5;
    const int l   = tid & 31;
    const int p0  = l*4;
    const int b   = blockIdx.x >> 4;
    const int n0  = (blockIdx.x & 15) << 7;

    for (int i = tid; i < 128; i += 256) { int c=i>>4, o=i&15; wW1t[i] = dk_g1[o]*dk_W1[o*8+c]; }
    if (tid < 16) wb1[tid] = dk_g1[tid]*dk_b1[tid] + dk_be1[tid];
    for (int i = tid; i < 512; i += 256) { int c=i>>5, o=i&31; wW2t[i] = dk_W2[o*16+c]; }
    if (tid < 32) wb2[tid] = dk_b2[tid];
    for (int i = tid; i < 512; i += 256) {
        int c = i >> 5, o = i & 31;
        float s = 0.f;
        #pragma unroll
        for (int j = 0; j < 32; j++) s += ff_W1[o*64 + j] * dk_W2[j*16 + c];
        wAh[c*32 + o] = ff_g1[o] * s;
    }
    if (tid < 32) {
        float s = 0.f;
        #pragma unroll
        for (int j = 0; j < 32; j++) s += ff_W1[tid*64 + j] * dk_b2[j];
        wbf[tid] = ff_be1[tid] + ff_g1[tid] * s;
    }
    for (int i = tid; i < 1024; i += 256) { int c=i>>5, o=i&31; wBg[i] = ff_g1[o]*ff_W1[o*64+32+c]; }
    for (int i = tid; i < 2048; i += 256) { int c=i>>6, o=i&63; wF2t[i] = ff_W2[o*32+c]; }
    if (tid < 64) wab[tid] = act_b[tid];
    for (int i = tid; i < 4096; i += 256) { int c=i>>6, o=i&63; wWEt[i] = edge_g[o]*edge_W[o*128+c]; }
    if (tid < 128) {
        const float* ap = appf + (((size_t)b*NN + n0 + tid)*NK + 0)*8;
        float4 a0 = *(const float4*)ap;
        float4 a1 = *(const float4*)(ap + 4);
        t_in[0*128+tid]=a0.x; t_in[1*128+tid]=a0.y; t_in[2*128+tid]=a0.z; t_in[3*128+tid]=a0.w;
        t_in[4*128+tid]=a1.x; t_in[5*128+tid]=a1.y; t_in[6*128+tid]=a1.z; t_in[7*128+tid]=a1.w;
    }
    __syncthreads();

    float mx[4][8];
    #pragma unroll
    for (int pp = 0; pp < 4; pp++)
        #pragma unroll
        for (int oo = 0; oo < 8; oo++) mx[pp][oo] = -1e30f;

    #pragma unroll 1
    for (int k = 0; k < NK; k++) {
        float4 gl[4];
        int idxr = 0;
        {
            const float* src = g_glT + (((size_t)b*NK + k)*32)*NN + n0;
            #pragma unroll
            for (int u = 0; u < 4; u++) {
                int f = (tid + u*256)*4;
                int c = f >> 7, col = f & 127;
                gl[u] = *(const float4*)&src[c*NN + col];
            }
        }
        if (tid < 128) idxr = g_idxT[((size_t)b*NK + k)*NN + n0 + tid];

        // GEMM1: dk1 [16x128], K=8
        {
            const int o0 = w*2;
            const u64 bias = *(const u64*)&wb1[o0];
            u64 a0 = bias, a1 = bias, a2 = bias, a3 = bias;
            #pragma unroll
            for (int c = 0; c < 8; c++) {
                u64 wv = *(const u64*)&wW1t[c*16 + o0];
                float4 bv = *(float4*)&t_in[c*128 + p0];
                ffma2(a0, wv, f2pack(bv.x, bv.x));
                ffma2(a1, wv, f2pack(bv.y, bv.y));
                ffma2(a2, wv, f2pack(bv.z, bv.z));
                ffma2(a3, wv, f2pack(bv.w, bv.w));
            }
            float l0,h0,l1,h1,l2,h2,l3,h3;
            f2unpack(a0,l0,h0); f2unpack(a1,l1,h1); f2unpack(a2,l2,h2); f2unpack(a3,l3,h3);
            *(float4*)&t_h[o0*128 + p0]     = make_float4(fmaxf(l0,0.f), fmaxf(l1,0.f), fmaxf(l2,0.f), fmaxf(l3,0.f));
            *(float4*)&t_h[(o0+1)*128 + p0] = make_float4(fmaxf(h0,0.f), fmaxf(h1,0.f), fmaxf(h2,0.f), fmaxf(h3,0.f));
        }
        {
            #pragma unroll
            for (int u = 0; u < 4; u++) {
                int f = (tid + u*256)*4;
                int c = f >> 7, col = f & 127;
                *(float4*)&t_rif[(32+c)*128 + col] = gl[u];
            }
        }
        if (tid < 128) s_idx[tid] = idxr;
        __syncthreads();   // A

        float4 a0n, a1n;
        if (tid < 128) {
            int kn = (k+1 < NK) ? k+1 : k;
            const float* ap = appf + (((size_t)b*NN + n0 + tid)*NK + kn)*8;
            a0n = *(const float4*)ap;
            a1n = *(const float4*)(ap + 4);
        }

        // GEMM2: dk2 [32x128], K=16
        {
            const int o0 = w*4;
            ulonglong2 bi = *(const ulonglong2*)&wb2[o0];
            u64 acc[4][2];
            #pragma unroll
            for (int pp = 0; pp < 4; pp++) { acc[pp][0] = bi.x; acc[pp][1] = bi.y; }
            #pragma unroll
            for (int c = 0; c < 16; c++) {
                ulonglong2 wv = *(const ulonglong2*)&wW2t[c*32 + o0];
                float4 bv = *(float4*)&t_h[c*128 + p0];
                u64 bx = f2pack(bv.x,bv.x), by = f2pack(bv.y,bv.y);
                u64 bz = f2pack(bv.z,bv.z), bw = f2pack(bv.w,bv.w);
                ffma2(acc[0][0], wv.x, bx); ffma2(acc[0][1], wv.y, bx);
                ffma2(acc[1][0], wv.x, by); ffma2(acc[1][1], wv.y, by);
                ffma2(acc[2][0], wv.x, bz); ffma2(acc[2][1], wv.y, bz);
                ffma2(acc[3][0], wv.x, bw); ffma2(acc[3][1], wv.y, bw);
            }
            #pragma unroll
            for (int pr = 0; pr < 2; pr++) {
                float l0,h0,l1,h1,l2,h2,l3,h3;
                f2unpack(acc[0][pr],l0,h0); f2unpack(acc[1][pr],l1,h1);
                f2unpack(acc[2][pr],l2,h2); f2unpack(acc[3][pr],l3,h3);
                *(float4*)&t_rif[(o0+2*pr)*128 + p0]   = make_float4(l0,l1,l2,l3);
                *(float4*)&t_rif[(o0+2*pr+1)*128 + p0] = make_float4(h0,h1,h2,h3);
            }
        }
        if (tid < 128) {
            t_in[0*128+tid]=a0n.x; t_in[1*128+tid]=a0n.y; t_in[2*128+tid]=a0n.z; t_in[3*128+tid]=a0n.w;
            t_in[4*128+tid]=a1n.x; t_in[5*128+tid]=a1n.y; t_in[6*128+tid]=a1n.z; t_in[7*128+tid]=a1n.w;
        }
        // GEMM3 (folded): att = wAh@h (16c) + wBg@glf (32c) + wbf
        {
            const int o0 = w*4;
            ulonglong2 bi = *(const ulonglong2*)&wbf[o0];
            u64 acc[4][2];
            #pragma unroll
            for (int pp = 0; pp < 4; pp++) { acc[pp][0] = bi.x; acc[pp][1] = bi.y; }
            #pragma unroll 4
            for (int c = 0; c < 16; c++) {
                ulonglong2 wv = *(const ulonglong2*)&wAh[c*32 + o0];
                float4 bv = *(float4*)&t_h[c*128 + p0];
                u64 bx = f2pack(bv.x,bv.x), by = f2pack(bv.y,bv.y);
                u64 bz = f2pack(bv.z,bv.z), bw = f2pack(bv.w,bv.w);
                ffma2(acc[0][0], wv.x, bx); ffma2(acc[0][1], wv.y, bx);
                ffma2(acc[1][0], wv.x, by); ffma2(acc[1][1], wv.y, by);
                ffma2(acc[2][0], wv.x, bz); ffma2(acc[2][1], wv.y, bz);
                ffma2(acc[3][0], wv.x, bw); ffma2(acc[3][1], wv.y, bw);
            }
            #pragma unroll 4
            for (int c = 0; c < 32; c++) {
                ulonglong2 wv = *(const ulonglong2*)&wBg[c*32 + o0];
                float4 bv = *(float4*)&t_rif[(32+c)*128 + p0];
                u64 bx = f2pack(bv.x,bv.x), by = f2pack(bv.y,bv.y);
                u64 bz = f2pack(bv.z,bv.z), bw = f2pack(bv.w,bv.w);
                ffma2(acc[0][0], wv.x, bx); ffma2(acc[0][1], wv.y, bx);
                ffma2(acc[1][0], wv.x, by); ffma2(acc[1][1], wv.y, by);
                ffma2(acc[2][0], wv.x, bz); ffma2(acc[2][1], wv.y, bz);
                ffma2(acc[3][0], wv.x, bw); ffma2(acc[3][1], wv.y, bw);
            }
            #pragma unroll
            for (int pr = 0; pr < 2; pr++) {
                float l0,h0,l1,h1,l2,h2,l3,h3;
                f2unpack(acc[0][pr],l0,h0); f2unpack(acc[1][pr],l1,h1);
                f2unpack(acc[2][pr],l2,h2); f2unpack(acc[3][pr],l3,h3);
                *(float4*)&t_att[(o0+2*pr)*128 + p0] =
                    make_float4(LEAKY(l0),LEAKY(l1),LEAKY(l2),LEAKY(l3));
                *(float4*)&t_att[(o0+2*pr+1)*128 + p0] =
                    make_float4(LEAKY(h0),LEAKY(h1),LEAKY(h2),LEAKY(h3));
            }
        }
        __syncthreads();   // B

        // GEMM4: ff2 [64x128], K=32; sigmoid; gate in place
        {
            const int o0 = w*8;
            u64 acc[4][4];
            #pragma unroll
            for (int pp = 0; pp < 4; pp++)
                #pragma unroll
                for (int pr = 0; pr < 4; pr++) acc[pp][pr] = 0ull;
            #pragma unroll 4
            for (int c = 0; c < 32; c++) {
                ulonglong2 wA = *(const ulonglong2*)&wF2t[c*64 + o0];
                ulonglong2 wB = *(const ulonglong2*)&wF2t[c*64 + o0 + 4];
                float4 bv = *(float4*)&t_att[c*128 + p0];
                u64 bx = f2pack(bv.x,bv.x), by = f2pack(bv.y,bv.y);
                u64 bz = f2pack(bv.z,bv.z), bw = f2pack(bv.w,bv.w);
                ffma2(acc[0][0], wA.x, bx); ffma2(acc[0][1], wA.y, bx);
                ffma2(acc[0][2], wB.x, bx); ffma2(acc[0][3], wB.y, bx);
                ffma2(acc[1][0], wA.x, by); ffma2(acc[1][1], wA.y, by);
                ffma2(acc[1][2], wB.x, by); ffma2(acc[1][3], wB.y, by);
                ffma2(acc[2][0], wA.x, bz); ffma2(acc[2][1], wA.y, bz);
                ffma2(acc[2][2], wB.x, bz); ffma2(acc[2][3], wB.y, bz);
                ffma2(acc[3][0], wA.x, bw); ffma2(acc[3][1], wA.y, bw);
                ffma2(acc[3][2], wB.x, bw); ffma2(acc[3][3], wB.y, bw);
            }
            #pragma unroll
            for (int hh = 0; hh < 2; hh++) {
                float sg[4][4];
                float bxv[4][4];
                #pragma unroll
                for (int pp = 0; pp < 4; pp++) {
                    float lo, hi;
                    f2unpack(acc[pp][2*hh],   lo, hi);
                    sg[pp][0] = 1.f/(1.f + __expf(-lo));
                    sg[pp][1] = 1.f/(1.f + __expf(-hi));
                    f2unpack(acc[pp][2*hh+1], lo, hi);
                    sg[pp][2] = 1.f/(1.f + __expf(-lo));
                    sg[pp][3] = 1.f/(1.f + __expf(-hi));
                    int j = s_idx[p0 + pp];
                    float4 gv = *(const float4*)(g_bxT + ((size_t)b*NN + j)*64 + o0 + 4*hh);
                    bxv[pp][0] = gv.x; bxv[pp][1] = gv.y; bxv[pp][2] = gv.z; bxv[pp][3] = gv.w;
                }
                #pragma unroll
                for (int oo = 0; oo < 4; oo++) {
                    int row = o0 + 4*hh + oo;
                    float ab = wab[row];
                    float4 rv = *(float4*)&t_rif[row*128 + p0];
                    rv.x = fmaxf(rv.x * sg[0][oo] * bxv[0][oo] + ab, 0.f);
                    rv.y = fmaxf(rv.y * sg[1][oo] * bxv[1][oo] + ab, 0.f);
                    rv.z = fmaxf(rv.z * sg[2][oo] * bxv[2][oo] + ab, 0.f);
                    rv.w = fmaxf(rv.w * sg[3][oo] * bxv[3][oo] + ab, 0.f);
                    *(float4*)&t_rif[row*128 + p0] = rv;
                }
            }
        }
        __syncthreads();   // C

        // GEMM5: edge [64x128], K=64; running max
        {
            const int o0 = w*8;
            u64 acc[4][4];
            #pragma unroll
            for (int pp = 0; pp < 4; pp++)
                #pragma unroll
                for (int pr = 0; pr < 4; pr++) acc[pp][pr] = 0ull;
            #pragma unroll 4
            for (int c = 0; c < 64; c++) {
                ulonglong2 wA = *(const ulonglong2*)&wWEt[c*64 + o0];
                ulonglong2 wB = *(const ulonglong2*)&wWEt[c*64 + o0 + 4];
                float4 bv = *(float4*)&t_rif[c*128 + p0];
                u64 bx = f2pack(bv.x,bv.x), by = f2pack(bv.y,bv.y);
                u64 bz = f2pack(bv.z,bv.z), bw = f2pack(bv.w,bv.w);
                ffma2(acc[0][0], wA.x, bx); ffma2(acc[0][1], wA.y, bx);
                ffma2(acc[0][2], wB.x, bx); ffma2(acc[0][3], wB.y, bx);
                ffma2(acc[1][0], wA.x, by); ffma2(acc[1][1], wA.y, by);
                ffma2(acc[1][2], wB.x, by); ffma2(acc[1][3], wB.y, by);
                ffma2(acc[2][0], wA.x, bz); ffma2(acc[2][1], wA.y, bz);
                ffma2(acc[2][2], wB.x, bz); ffma2(acc[2][3], wB.y, bz);
                ffma2(acc[3][0], wA.x, bw); ffma2(acc[3][1], wA.y, bw);
                ffma2(acc[3][2], wB.x, bw); ffma2(acc[3][3], wB.y, bw);
            }
            #pragma unroll
            for (int pp = 0; pp < 4; pp++) {
                #pragma unroll
                for (int pr = 0; pr < 4; pr++) {
                    float lo, hi;
                    f2unpack(acc[pp][pr], lo, hi);
                    mx[pp][2*pr]   = fmaxf(mx[pp][2*pr],   lo);
                    mx[pp][2*pr+1] = fmaxf(mx[pp][2*pr+1], hi);
                }
            }
        }
        __syncthreads();   // D
    }

    // epilogue: out = leaky(mx + cst)
    {
        const int o0 = w*8;
        #pragma unroll
        for (int hh = 0; hh < 2; hh++) {
            float cc[4][4];
            #pragma unroll
            for (int pp = 0; pp < 4; pp++) {
                float4 cv = *(const float4*)(g_cst + ((size_t)b*NN + n0 + p0 + pp)*64 + o0 + 4*hh);
                cc[pp][0]=cv.x; cc[pp][1]=cv.y; cc[pp][2]=cv.z; cc[pp][3]=cv.w;
            }
            #pragma unroll
            for (int oo = 0; oo < 4; oo++) {
                int row = o0 + 4*hh + oo;
                float4 v;
                v.x = LEAKY(mx[0][4*hh+oo] + cc[0][oo]);
                v.y = LEAKY(mx[1][4*hh+oo] + cc[1][oo]);
                v.z = LEAKY(mx[2][4*hh+oo] + cc[2][oo]);
                v.w = LEAKY(mx[3][4*hh+oo] + cc[3][oo]);
                *(float4*)&out[((size_t)b*64 + row)*NN + n0 + p0] = v;
            }
        }
    }
}

// =====================================================================
extern "C" void kernel_launch(void* const* d_in, const int* in_sizes, int n_in,
                              void* d_out, int out_size)
{
    const float* pos     = (const float*)d_in[0];
    const float* x       = (const float*)d_in[1];
    const float* glf     = (const float*)d_in[2];
    const float* appf    = (const float*)d_in[3];
    const float* basis_W = (const float*)d_in[4];
    const float* dk_W1   = (const float*)d_in[5];
    const float* dk_b1   = (const float*)d_in[6];
    const float* dk_g1   = (const float*)d_in[7];
    const float* dk_be1  = (const float*)d_in[8];
    const float* dk_W2   = (const float*)d_in[9];
    const float* dk_b2   = (const float*)d_in[10];
    const float* act_g   = (const float*)d_in[11];
    const float* act_b   = (const float*)d_in[12];
    const float* ff_W1   = (const float*)d_in[13];
    const float* ff_g1   = (const float*)d_in[14];
    const float* ff_be1  = (const float*)d_in[15];
    const float* ff_W2   = (const float*)d_in[16];
    const float* edge_W  = (const float*)d_in[17];
    const float* edge_g  = (const float*)d_in[18];
    const float* edge_be = (const float*)d_in[19];
    float* out = (float*)d_out;

    knn_kernel<<<dim3(NN/32, NB), 256>>>(pos);
    prep_kernel<<<(NB*NN)/128, 128>>>(x, basis_W, edge_W, act_g, edge_g, edge_be);
    tr_kernel<<<dim3(NN/64, 32, NB), 256>>>(glf);

    const int smem_bytes = (128+16+512+32+512+32+1024+2048+64+4096 + 1024+2048+8192+4096 + 128) * (int)sizeof(float);
    cudaFuncSetAttribute(main_kernel, cudaFuncAttributeMaxDynamicSharedMemorySize, smem_bytes);
    main_kernel<<<NB*NN/128, 256, smem_bytes>>>(appf,
                                                dk_W1, dk_b1, dk_g1, dk_be1,
                                                dk_W2, dk_b2, act_b,
                                                ff_W1, ff_g1, ff_be1, ff_W2,
                                                edge_W, edge_g, out);
}